// round 8
// baseline (speedup 1.0000x reference)
#include <cuda_runtime.h>
#include <cuda_bf16.h>

#define N_STARS 2048
#define BATCH   256
#define PF      28
#define NGE     512
#define GF      32
#define KTOT    60        // PF + GF
#define OPD2    65536     // 256*256

// Scratch (no device allocation allowed -> __device__ globals)
__device__ float g_W[KTOT * BATCH];   // W[k][b], k-major

// ---------------------------------------------------------------------------
// Stage 1: index search + W = [poly_dic[idx] @ alpha_poly | graph_dic[idx] @ alpha_graph]
// One block per query position b. 256 threads.  (unchanged; passing since R3)
// ---------------------------------------------------------------------------
__global__ __launch_bounds__(256) void prep_kernel(
    const float* __restrict__ positions, const float* __restrict__ obs_pos,
    const float* __restrict__ poly_dic,  const float* __restrict__ graph_dic,
    const float* __restrict__ alpha_poly,const float* __restrict__ alpha_graph)
{
    int b = blockIdx.x;
    int t = threadIdx.x;

    __shared__ int   s_min;
    __shared__ float s_row[NGE];
    __shared__ float s_prow[PF];
    __shared__ float s_part[8][32];

    if (t == 0) s_min = N_STARS;
    __syncthreads();

    float px = positions[2 * b], py = positions[2 * b + 1];
    int local = N_STARS;
    for (int n = t; n < N_STARS; n += 256) {
        float ox = obs_pos[2 * n], oy = obs_pos[2 * n + 1];
        if (ox == px || oy == py) { local = n; break; }
    }
    if (local < N_STARS) atomicMin(&s_min, local);
    __syncthreads();
    int idx = (s_min < N_STARS) ? s_min : 0;

    for (int g = t; g < NGE; g += 256) s_row[g] = graph_dic[(size_t)idx * NGE + g];
    if (t < PF) s_prow[t] = poly_dic[(size_t)idx * PF + t];
    __syncthreads();

    {
        int kg = t & 31, sl = t >> 5;
        float acc = 0.f;
        int g0 = sl * 64;
        #pragma unroll 8
        for (int i = 0; i < 64; i++) {
            int g = g0 + i;
            acc += s_row[g] * alpha_graph[g * GF + kg];
        }
        s_part[sl][kg] = acc;
    }
    __syncthreads();

    if (t < GF) {
        float acc = 0.f;
        #pragma unroll
        for (int sl = 0; sl < 8; sl++) acc += s_part[sl][t];
        g_W[(PF + t) * BATCH + b] = acc;
    } else if (t < GF + PF) {
        int k = t - GF;
        float acc = 0.f;
        #pragma unroll
        for (int p = 0; p < PF; p++) acc += s_prow[p] * alpha_poly[p * PF + k];
        g_W[k * BATCH + b] = acc;
    }
}

// ---------------------------------------------------------------------------
// Stage 2: C[b][e] = sum_k W[b][k] * S[k][e]   (B=256, E=65536, K=60)
// CTA tile 128e x 64b, 256 threads, 3 CTAs/SM (smem 61.4KB, regs <= 85).
// Thread micro-tile 8e x 4b: 16 FFMA2 + 4 LDS.128 per k.
// S rows use a 16B-slot XOR swizzle (s ^= (s>>3)&1) for conflict-free access
// with zero padding. W stored natural + pair-swapped for the cross products.
// ---------------------------------------------------------------------------
#define SMEM_FLOATS (KTOT * (128 + 64 + 64))
#define SMEM_BYTES  (SMEM_FLOATS * 4)       // 61440

typedef unsigned long long ull;

__device__ __forceinline__ void ffma2(ull &d, ull a, ull b_) {
    asm("fma.rn.f32x2 %0, %1, %2, %0;" : "+l"(d) : "l"(a), "l"(b_));
}
__device__ __forceinline__ float2 u2f(ull u) {
    float2 f;
    asm("mov.b64 {%0,%1}, %2;" : "=f"(f.x), "=f"(f.y) : "l"(u));
    return f;
}
__device__ __forceinline__ int swz(int slot) {        // 16B-slot swizzle
    return slot ^ ((slot >> 3) & 1);
}

__global__ void __launch_bounds__(256, 3) mccd_main(
    const float* __restrict__ S_poly, const float* __restrict__ S_graph,
    float* __restrict__ out)
{
    extern __shared__ float smem[];
    float* sS  = smem;                      // [KTOT][128]  swizzled 16B slots
    float* sWn = smem + KTOT * 128;         // [KTOT][64]   natural pairs
    float* sWs = sWn  + KTOT * 64;          // [KTOT][64]   pair-swapped

    int tid    = threadIdx.x;
    int e_base = blockIdx.x * 128;
    int b_base = blockIdx.y * 64;

    // ---- stage (coalesced global reads; whole K fits, single phase) ----
    for (int idx = tid; idx < KTOT * 128; idx += 256) {
        int k = idx >> 7, j = idx & 127;
        float sv = (k < PF) ? S_poly [(size_t)k        * OPD2 + e_base + j]
                            : S_graph[(size_t)(k - PF) * OPD2 + e_base + j];
        sS[k * 128 + swz(j >> 2) * 4 + (j & 3)] = sv;
    }
    for (int idx = tid; idx < KTOT * 64; idx += 256) {
        int k = idx >> 6, j = idx & 63;
        float w = g_W[k * BATCH + b_base + j];
        sWn[k * 64 + j]       = w;
        sWs[k * 64 + (j ^ 1)] = w;
    }
    __syncthreads();

    int lane = tid & 31, wid = tid >> 5;
    int we = wid & 1, wb = wid >> 1;        // warp grid: 2 e-warps x 4 b-warps
    int eg = lane & 7, bg = lane >> 3;      // lane grid: 8 e-groups x 4 b-groups

    int c = we * 8 + eg;                    // S chunk 0..15 (8 floats each)
    const float* spA = sS  + swz(2 * c)     * 4;   // floats [8c, 8c+4)
    const float* spB = sS  + swz(2 * c + 1) * 4;   // floats [8c+4, 8c+8)
    const float* wpn = sWn + (wb * 4 + bg) * 4;    // 4 b-values, 16B aligned
    const float* wps = sWs + (wb * 4 + bg) * 4;

    ull ad[4][2] = {}, ax[4][2] = {};       // diag / cross accumulator pairs

    #pragma unroll 12
    for (int k = 0; k < KTOT; k++) {
        ulonglong2 sA = *reinterpret_cast<const ulonglong2*>(spA + k * 128);
        ulonglong2 sB = *reinterpret_cast<const ulonglong2*>(spB + k * 128);
        ulonglong2 nv = *reinterpret_cast<const ulonglong2*>(wpn + k * 64);
        ulonglong2 xv = *reinterpret_cast<const ulonglong2*>(wps + k * 64);
        ull su[4] = { sA.x, sA.y, sB.x, sB.y };   // (s0,s1)(s2,s3)(s4,s5)(s6,s7)
        ull wn[2] = { nv.x, nv.y };               // (w0,w1)(w2,w3)
        ull ws[2] = { xv.x, xv.y };               // (w1,w0)(w3,w2)
        #pragma unroll
        for (int p = 0; p < 4; p++) {
            #pragma unroll
            for (int q = 0; q < 2; q++) {
                ffma2(ad[p][q], su[p], wn[q]);    // (e2p,b2q) , (e2p+1,b2q+1)
                ffma2(ax[p][q], su[p], ws[q]);    // (e2p,b2q+1), (e2p+1,b2q)
            }
        }
    }

    // ---- epilogue: unscramble diag/cross pairs, 128-bit stores ----
    int e0 = e_base + we * 64 + eg * 8;
    int b0 = b_base + wb * 16 + bg * 4;
    #pragma unroll
    for (int q = 0; q < 2; q++) {
        float* r0 = out + (size_t)(b0 + 2 * q)     * OPD2 + e0;  // even b row
        float* r1 = out + (size_t)(b0 + 2 * q + 1) * OPD2 + e0;  // odd  b row
        float v[8], u[8];
        #pragma unroll
        for (int p = 0; p < 4; p++) {
            float2 d = u2f(ad[p][q]);   // (c[e2p,b2q]  , c[e2p+1,b2q+1])
            float2 x = u2f(ax[p][q]);   // (c[e2p,b2q+1], c[e2p+1,b2q]  )
            v[2 * p] = d.x;  v[2 * p + 1] = x.y;
            u[2 * p] = x.x;  u[2 * p + 1] = d.y;
        }
        *reinterpret_cast<float4*>(r0)     = make_float4(v[0], v[1], v[2], v[3]);
        *reinterpret_cast<float4*>(r0 + 4) = make_float4(v[4], v[5], v[6], v[7]);
        *reinterpret_cast<float4*>(r1)     = make_float4(u[0], u[1], u[2], u[3]);
        *reinterpret_cast<float4*>(r1 + 4) = make_float4(u[4], u[5], u[6], u[7]);
    }
}

// ---------------------------------------------------------------------------
extern "C" void kernel_launch(void* const* d_in, const int* in_sizes, int n_in,
                              void* d_out, int out_size) {
    const float* positions   = (const float*)d_in[0];
    const float* obs_pos     = (const float*)d_in[1];
    const float* poly_dic    = (const float*)d_in[2];
    const float* graph_dic   = (const float*)d_in[3];
    const float* alpha_poly  = (const float*)d_in[4];
    const float* alpha_graph = (const float*)d_in[5];
    const float* S_poly      = (const float*)d_in[6];
    const float* S_graph     = (const float*)d_in[7];
    float* out = (float*)d_out;

    cudaFuncSetAttribute(mccd_main, cudaFuncAttributeMaxDynamicSharedMemorySize,
                         SMEM_BYTES);

    prep_kernel<<<BATCH, 256>>>(positions, obs_pos, poly_dic, graph_dic,
                                alpha_poly, alpha_graph);
    mccd_main<<<dim3(OPD2 / 128, BATCH / 64), 256, SMEM_BYTES>>>(S_poly, S_graph, out);
}

// round 9
// speedup vs baseline: 1.3597x; 1.3597x over previous
#include <cuda_runtime.h>
#include <cuda_bf16.h>

#define N_STARS 2048
#define BATCH   256
#define PF      28
#define NGE     512
#define GF      32
#define KTOT    60        // PF + GF
#define OPD2    65536     // 256*256

// Scratch (no device allocation allowed -> __device__ globals)
__device__ float g_W[KTOT * BATCH];   // W[k][b], k-major

// ---------------------------------------------------------------------------
// Stage 1: index search + W = [poly_dic[idx] @ alpha_poly | graph_dic[idx] @ alpha_graph]
// One block per query position b. 256 threads.  (unchanged; passing since R3)
// ---------------------------------------------------------------------------
__global__ __launch_bounds__(256) void prep_kernel(
    const float* __restrict__ positions, const float* __restrict__ obs_pos,
    const float* __restrict__ poly_dic,  const float* __restrict__ graph_dic,
    const float* __restrict__ alpha_poly,const float* __restrict__ alpha_graph)
{
    int b = blockIdx.x;
    int t = threadIdx.x;

    __shared__ int   s_min;
    __shared__ float s_row[NGE];
    __shared__ float s_prow[PF];
    __shared__ float s_part[8][32];

    if (t == 0) s_min = N_STARS;
    __syncthreads();

    float px = positions[2 * b], py = positions[2 * b + 1];
    int local = N_STARS;
    for (int n = t; n < N_STARS; n += 256) {
        float ox = obs_pos[2 * n], oy = obs_pos[2 * n + 1];
        if (ox == px || oy == py) { local = n; break; }
    }
    if (local < N_STARS) atomicMin(&s_min, local);
    __syncthreads();
    int idx = (s_min < N_STARS) ? s_min : 0;

    for (int g = t; g < NGE; g += 256) s_row[g] = graph_dic[(size_t)idx * NGE + g];
    if (t < PF) s_prow[t] = poly_dic[(size_t)idx * PF + t];
    __syncthreads();

    {
        int kg = t & 31, sl = t >> 5;
        float acc = 0.f;
        int g0 = sl * 64;
        #pragma unroll 8
        for (int i = 0; i < 64; i++) {
            int g = g0 + i;
            acc += s_row[g] * alpha_graph[g * GF + kg];
        }
        s_part[sl][kg] = acc;
    }
    __syncthreads();

    if (t < GF) {
        float acc = 0.f;
        #pragma unroll
        for (int sl = 0; sl < 8; sl++) acc += s_part[sl][t];
        g_W[(PF + t) * BATCH + b] = acc;
    } else if (t < GF + PF) {
        int k = t - GF;
        float acc = 0.f;
        #pragma unroll
        for (int p = 0; p < PF; p++) acc += s_prow[p] * alpha_poly[p * PF + k];
        g_W[k * BATCH + b] = acc;
    }
}

// ---------------------------------------------------------------------------
// Stage 2: C[b][e] = sum_k W[b][k] * S[k][e]   (B=256, E=65536, K=60)
// CTA tile 128e x 64b, 128 threads, 3 CTAs/SM (smem 61.4KB, <=170 regs).
// Thread micro-tile 8e x 8b: 32 FFMA2 + 6 LDS.128 per k.
// W stored as duplicated (w,w) pairs -> all accumulator pairs are (e,e):
// natural output layout, zero epilogue unscramble.
// Explicit register double-buffering prefetches k+1 before k's FMAs.
// ---------------------------------------------------------------------------
#define SMEM_FLOATS (KTOT * (128 + 128))
#define SMEM_BYTES  (SMEM_FLOATS * 4)       // 61440

typedef unsigned long long ull;

__device__ __forceinline__ void ffma2(ull &d, ull a, ull b_) {
    asm("fma.rn.f32x2 %0, %1, %2, %0;" : "+l"(d) : "l"(a), "l"(b_));
}
__device__ __forceinline__ int swz(int slot) {        // 16B-slot swizzle
    return slot ^ ((slot >> 3) & 1);
}

#define LOADK(B, KK) do {                                                        \
    ulonglong2 _a  = *reinterpret_cast<const ulonglong2*>(spA + (KK) * 128);     \
    ulonglong2 _b  = *reinterpret_cast<const ulonglong2*>(spB + (KK) * 128);     \
    ulonglong2 _w0 = *reinterpret_cast<const ulonglong2*>(wp  + (KK) * 128);     \
    ulonglong2 _w1 = *reinterpret_cast<const ulonglong2*>(wp  + (KK) * 128 + 4); \
    ulonglong2 _w2 = *reinterpret_cast<const ulonglong2*>(wp  + (KK) * 128 + 8); \
    ulonglong2 _w3 = *reinterpret_cast<const ulonglong2*>(wp  + (KK) * 128 + 12);\
    su[B][0] = _a.x;  su[B][1] = _a.y;  su[B][2] = _b.x;  su[B][3] = _b.y;       \
    wd[B][0] = _w0.x; wd[B][1] = _w0.y; wd[B][2] = _w1.x; wd[B][3] = _w1.y;      \
    wd[B][4] = _w2.x; wd[B][5] = _w2.y; wd[B][6] = _w3.x; wd[B][7] = _w3.y;      \
} while (0)

#define FMAK(B) do {                                                             \
    _Pragma("unroll")                                                            \
    for (int _p = 0; _p < 4; _p++) {                                             \
        _Pragma("unroll")                                                        \
        for (int _q = 0; _q < 8; _q++)                                           \
            ffma2(acc[_p][_q], su[B][_p], wd[B][_q]);                            \
    }                                                                            \
} while (0)

__global__ void __launch_bounds__(128, 3) mccd_main(
    const float* __restrict__ S_poly, const float* __restrict__ S_graph,
    float* __restrict__ out)
{
    extern __shared__ float smem[];
    float* sS = smem;                       // [KTOT][128]  swizzled 16B slots
    float* sW = smem + KTOT * 128;          // [KTOT][128]  duplicated (w,w) pairs

    int tid    = threadIdx.x;
    int e_base = blockIdx.x * 128;
    int b_base = blockIdx.y * 64;

    // ---- stage: one full k-row per loop iter (coalesced 512B global reads) ----
    int s_off = swz(tid >> 2) * 4 + (tid & 3);
    int w_src = tid >> 1;                   // b-index duplicated into pairs
    #pragma unroll 4
    for (int k = 0; k < KTOT; k++) {
        float sv = (k < PF) ? S_poly [(size_t)k        * OPD2 + e_base + tid]
                            : S_graph[(size_t)(k - PF) * OPD2 + e_base + tid];
        sS[k * 128 + s_off] = sv;
        sW[k * 128 + tid]   = g_W[k * BATCH + b_base + w_src];
    }
    __syncthreads();

    int te = tid & 15;                      // 16 e-groups of 8 floats
    int tb = tid >> 4;                      // 8 b-groups of 8 b-values

    const float* spA = sS + swz(2 * te)     * 4;   // floats [8te, 8te+4)
    const float* spB = sS + swz(2 * te + 1) * 4;   // floats [8te+4, 8te+8)
    const float* wp  = sW + tb * 16;               // 8 dup pairs, broadcast loads

    ull acc[4][8] = {};                     // [e-pair][b]
    ull su[2][4], wd[2][8];                 // double-buffered operands

    LOADK(0, 0);
    #pragma unroll 4
    for (int k = 0; k < KTOT - 2; k += 2) {
        LOADK(1, k + 1);
        FMAK(0);
        LOADK(0, k + 2);
        FMAK(1);
    }
    LOADK(1, KTOT - 1);
    FMAK(0);
    FMAK(1);

    // ---- epilogue: natural (e,e) pairs, 16B stores, 512B/warp coalesced ----
    size_t base = (size_t)(b_base + tb * 8) * OPD2 + (size_t)e_base + te * 8;
    #pragma unroll
    for (int q = 0; q < 8; q++) {
        float* r = out + base + (size_t)q * OPD2;
        ulonglong2 v0; v0.x = acc[0][q]; v0.y = acc[1][q];
        ulonglong2 v1; v1.x = acc[2][q]; v1.y = acc[3][q];
        *reinterpret_cast<ulonglong2*>(r)     = v0;
        *reinterpret_cast<ulonglong2*>(r + 4) = v1;
    }
}

// ---------------------------------------------------------------------------
extern "C" void kernel_launch(void* const* d_in, const int* in_sizes, int n_in,
                              void* d_out, int out_size) {
    const float* positions   = (const float*)d_in[0];
    const float* obs_pos     = (const float*)d_in[1];
    const float* poly_dic    = (const float*)d_in[2];
    const float* graph_dic   = (const float*)d_in[3];
    const float* alpha_poly  = (const float*)d_in[4];
    const float* alpha_graph = (const float*)d_in[5];
    const float* S_poly      = (const float*)d_in[6];
    const float* S_graph     = (const float*)d_in[7];
    float* out = (float*)d_out;

    cudaFuncSetAttribute(mccd_main, cudaFuncAttributeMaxDynamicSharedMemorySize,
                         SMEM_BYTES);

    prep_kernel<<<BATCH, 256>>>(positions, obs_pos, poly_dic, graph_dic,
                                alpha_poly, alpha_graph);
    mccd_main<<<dim3(OPD2 / 128, BATCH / 64), 128, SMEM_BYTES>>>(S_poly, S_graph, out);
}

// round 13
// speedup vs baseline: 1.8673x; 1.3733x over previous
#include <cuda_runtime.h>
#include <cuda_bf16.h>
#include <cstdint>

#define N_STARS 2048
#define BATCH   256
#define PF      28
#define NGE     512
#define GF      32
#define KTOT    60        // PF + GF
#define KPAD    64        // zero-padded K for MMA
#define OPD2    65536     // 256*256

// Scratch (no device allocation allowed -> __device__ globals)
__device__ float g_W[KTOT * BATCH];   // W[k][b], k-major

// ---------------------------------------------------------------------------
// Stage 1: index search + W construction (unchanged; passing since R3)
// ---------------------------------------------------------------------------
__global__ __launch_bounds__(256) void prep_kernel(
    const float* __restrict__ positions, const float* __restrict__ obs_pos,
    const float* __restrict__ poly_dic,  const float* __restrict__ graph_dic,
    const float* __restrict__ alpha_poly,const float* __restrict__ alpha_graph)
{
    int b = blockIdx.x;
    int t = threadIdx.x;

    __shared__ int   s_min;
    __shared__ float s_row[NGE];
    __shared__ float s_prow[PF];
    __shared__ float s_part[8][32];

    if (t == 0) s_min = N_STARS;
    __syncthreads();

    float px = positions[2 * b], py = positions[2 * b + 1];
    int local = N_STARS;
    for (int n = t; n < N_STARS; n += 256) {
        float ox = obs_pos[2 * n], oy = obs_pos[2 * n + 1];
        if (ox == px || oy == py) { local = n; break; }
    }
    if (local < N_STARS) atomicMin(&s_min, local);
    __syncthreads();
    int idx = (s_min < N_STARS) ? s_min : 0;

    for (int g = t; g < NGE; g += 256) s_row[g] = graph_dic[(size_t)idx * NGE + g];
    if (t < PF) s_prow[t] = poly_dic[(size_t)idx * PF + t];
    __syncthreads();

    {
        int kg = t & 31, sl = t >> 5;
        float acc = 0.f;
        int g0 = sl * 64;
        #pragma unroll 8
        for (int i = 0; i < 64; i++) {
            int g = g0 + i;
            acc += s_row[g] * alpha_graph[g * GF + kg];
        }
        s_part[sl][kg] = acc;
    }
    __syncthreads();

    if (t < GF) {
        float acc = 0.f;
        #pragma unroll
        for (int sl = 0; sl < 8; sl++) acc += s_part[sl][t];
        g_W[(PF + t) * BATCH + b] = acc;
    } else if (t < GF + PF) {
        int k = t - GF;
        float acc = 0.f;
        #pragma unroll
        for (int p = 0; p < PF; p++) acc += s_prow[p] * alpha_poly[p * PF + k];
        g_W[k * BATCH + b] = acc;
    }
}

// ---------------------------------------------------------------------------
// Stage 2: C[b][e] = sum_k W[b][k] * S[k][e] via mma.sync m16n8k8 tf32,
// hi/lo split, 3 passes -> ~fp32 accuracy. CTA tile 128e x 128b, 8 warps,
// warp tile 32b x 64e. smem tiles stored [k][.] stride 136 floats:
// staging = float4 coalesced conflict-free; fragment loads bank-perfect
// ((8*tig + g) mod 32 is a permutation).
// ---------------------------------------------------------------------------
#define SROW 136
#define SMEM_BYTES (2 * KPAD * SROW * 4)   // 69632

__device__ __forceinline__ void mma_tf32(float* d, const uint32_t* a, const uint32_t* b) {
    asm volatile(
        "mma.sync.aligned.m16n8k8.row.col.f32.tf32.tf32.f32 "
        "{%0,%1,%2,%3}, {%4,%5,%6,%7}, {%8,%9}, {%0,%1,%2,%3};"
        : "+f"(d[0]), "+f"(d[1]), "+f"(d[2]), "+f"(d[3])
        : "r"(a[0]), "r"(a[1]), "r"(a[2]), "r"(a[3]), "r"(b[0]), "r"(b[1]));
}
__device__ __forceinline__ void hilo(float v, uint32_t& h, uint32_t& l) {
    h = __float_as_uint(v) & 0xFFFFE000u;            // exact tf32 value
    l = __float_as_uint(v - __uint_as_float(h));     // exact remainder (tf32-truncated by HW)
}

__global__ void __launch_bounds__(256, 2) mccd_mma(
    const float* __restrict__ S_poly, const float* __restrict__ S_graph,
    float* __restrict__ out)
{
    extern __shared__ float smem[];
    float* sS = smem;                 // [KPAD][SROW] : S[k][e_tile]
    float* sW = smem + KPAD * SROW;   // [KPAD][SROW] : W[k][b_tile]

    int tid    = threadIdx.x;
    int e_base = blockIdx.x * 128;
    int b_base = blockIdx.y * 128;

    // ---- stage: float4 coalesced global reads, conflict-free smem writes ----
    {
        int l4 = (tid & 31) * 4;
        int kw = tid >> 5;
        #pragma unroll
        for (int kk = kw; kk < KPAD; kk += 8) {
            float4 sv = make_float4(0.f, 0.f, 0.f, 0.f);
            float4 wv = make_float4(0.f, 0.f, 0.f, 0.f);
            if (kk < PF)
                sv = *reinterpret_cast<const float4*>(&S_poly[(size_t)kk * OPD2 + e_base + l4]);
            else if (kk < KTOT)
                sv = *reinterpret_cast<const float4*>(&S_graph[(size_t)(kk - PF) * OPD2 + e_base + l4]);
            if (kk < KTOT)
                wv = *reinterpret_cast<const float4*>(&g_W[kk * BATCH + b_base + l4]);
            *reinterpret_cast<float4*>(&sS[kk * SROW + l4]) = sv;
            *reinterpret_cast<float4*>(&sW[kk * SROW + l4]) = wv;
        }
    }
    __syncthreads();

    int lane = tid & 31, w = tid >> 5;
    int g  = lane >> 2;               // 0..7
    int tg = lane & 3;                // 0..3
    int b0w = (w & 3) * 32;           // warp b-offset within CTA tile
    int e0w = (w >> 2) * 64;          // warp e-offset within CTA tile

    float acc[2][8][4] = {};          // [m-tile][n-tile][frag]

    #pragma unroll
    for (int kt = 0; kt < 8; kt++) {
        const float* kr = sS + (8 * kt + tg) * SROW;   // B rows k = 8kt+tg (+4)
        const float* wr = sW + (8 * kt + tg) * SROW;

        // A fragments (16b x 8k), 2 m-tiles, hi/lo
        uint32_t ahi[2][4], alo[2][4];
        #pragma unroll
        for (int mt = 0; mt < 2; mt++) {
            int bo = b0w + 16 * mt + g;
            hilo(wr[bo],              ahi[mt][0], alo[mt][0]);
            hilo(wr[bo + 8],          ahi[mt][1], alo[mt][1]);
            hilo(wr[4 * SROW + bo],     ahi[mt][2], alo[mt][2]);
            hilo(wr[4 * SROW + bo + 8], ahi[mt][3], alo[mt][3]);
        }

        // B fragments in two halves of 4 n-tiles (register pressure)
        #pragma unroll
        for (int h = 0; h < 2; h++) {
            uint32_t bhi[4][2], blo[4][2];
            #pragma unroll
            for (int q = 0; q < 4; q++) {
                int eo = e0w + (h * 4 + q) * 8 + g;
                hilo(kr[eo],            bhi[q][0], blo[q][0]);
                hilo(kr[4 * SROW + eo], bhi[q][1], blo[q][1]);
            }
            #pragma unroll
            for (int mt = 0; mt < 2; mt++)
                #pragma unroll
                for (int q = 0; q < 4; q++)
                    mma_tf32(acc[mt][h * 4 + q], ahi[mt], bhi[q]);
            #pragma unroll
            for (int mt = 0; mt < 2; mt++)
                #pragma unroll
                for (int q = 0; q < 4; q++)
                    mma_tf32(acc[mt][h * 4 + q], ahi[mt], blo[q]);
            #pragma unroll
            for (int mt = 0; mt < 2; mt++)
                #pragma unroll
                for (int q = 0; q < 4; q++)
                    mma_tf32(acc[mt][h * 4 + q], alo[mt], bhi[q]);
        }
    }

    // ---- epilogue: d frags -> out[b][e], float2 (32B-sector) stores ----
    #pragma unroll
    for (int mt = 0; mt < 2; mt++) {
        #pragma unroll
        for (int nt = 0; nt < 8; nt++) {
            size_t b = (size_t)(b_base + b0w + 16 * mt + g);
            size_t e = (size_t)(e_base + e0w + 8 * nt + 2 * tg);
            *reinterpret_cast<float2*>(&out[b * OPD2 + e])
                = make_float2(acc[mt][nt][0], acc[mt][nt][1]);
            *reinterpret_cast<float2*>(&out[(b + 8) * OPD2 + e])
                = make_float2(acc[mt][nt][2], acc[mt][nt][3]);
        }
    }
}

// ---------------------------------------------------------------------------
extern "C" void kernel_launch(void* const* d_in, const int* in_sizes, int n_in,
                              void* d_out, int out_size) {
    const float* positions   = (const float*)d_in[0];
    const float* obs_pos     = (const float*)d_in[1];
    const float* poly_dic    = (const float*)d_in[2];
    const float* graph_dic   = (const float*)d_in[3];
    const float* alpha_poly  = (const float*)d_in[4];
    const float* alpha_graph = (const float*)d_in[5];
    const float* S_poly      = (const float*)d_in[6];
    const float* S_graph     = (const float*)d_in[7];
    float* out = (float*)d_out;

    cudaFuncSetAttribute(mccd_mma, cudaFuncAttributeMaxDynamicSharedMemorySize,
                         SMEM_BYTES);

    prep_kernel<<<BATCH, 256>>>(positions, obs_pos, poly_dic, graph_dic,
                                alpha_poly, alpha_graph);
    mccd_mma<<<dim3(OPD2 / 128, BATCH / 128), 256, SMEM_BYTES>>>(S_poly, S_graph, out);
}